// round 15
// baseline (speedup 1.0000x reference)
#include <cuda_runtime.h>
#include <cuda_fp16.h>
#include <cstdint>

#define NN 4096
#define TT 64
#define DIN_ 131
#define GIN_ 132
#define NCTA 256
#define A_ST 18432              // diffusion A stage: 128 x 72 halves
#define B_ST 17408              // diffusion B stage: 64 x 136 halves
#define DSM_BYTES (2 * (A_ST + B_ST))   // 71680

// ---------------- static device workspace ----------------
__device__ __half d_Ah[(size_t)NN * NN];      // row-normalized A fp16 (33.5 MB)
__device__ __half d_A2[(size_t)NN * NN];      // Anorm^2 fp16 (33.5 MB)
__device__ float  d_Dfac[NN];                 // D/(D+1e-8)
__device__ __half d_U16[NN * 256];            // [n][c*64+t] c=m,tf,tj; cols 192.. zero
__device__ __half d_P1[NN * 256];             // Anorm @ U
__device__ __half d_P2[NN * 256];             // Anorm^2 @ U
__device__ __half d_S[NN * 384];              // [h | G1 | G2]
__device__ __half d_X[NN * 256];              // [msg | h]
__device__ float  d_hst[NN * 128];            // carried state fp32
__device__ float  d_logit[NN * 4];            // h @ mixW^T (raw, prev step)
__device__ float  d_M4[(size_t)NN * 512];     // S @ Wcat
__device__ float  d_GG[(size_t)NN * 768];     // [gi_msg | gh]
__device__ float  d_Part[(size_t)4 * NN * 256]; // split-K partials (16.8 MB)
__device__ __half d_Wcat[384 * 512];          // folded Cheb weights
__device__ float  d_WuC[3 * 3 * 4 * 128];     // folded Cheb weights (u part)
__device__ __half d_Wblk[256 * 768];          // block-diag [Wihm ; Whh]
__device__ unsigned d_barCnt;
__device__ unsigned d_barGen;

#define CPA16(dst, src) asm volatile("cp.async.cg.shared.global [%0], [%1], 16;\n" :: "r"(dst), "l"(src))
#define CPCOMMIT() asm volatile("cp.async.commit_group;\n" ::)

__device__ __forceinline__ float ldcg(const float* p) {
    float v;
    asm volatile("ld.global.cg.f32 %0,[%1];" : "=f"(v) : "l"(p));
    return v;
}
__device__ __forceinline__ float4 ldcg4(const float* p) {
    float4 v;
    asm volatile("ld.global.cg.v4.f32 {%0,%1,%2,%3},[%4];"
                 : "=f"(v.x), "=f"(v.y), "=f"(v.z), "=f"(v.w) : "l"(p));
    return v;
}

// ---------------- bounded grid barrier (all 256 CTAs resident) ------------------
__device__ __forceinline__ void gridbar() {
    __syncthreads();
    if (threadIdx.x == 0) {
        __threadfence();
        volatile unsigned* genp = &d_barGen;
        unsigned g = *genp;
        unsigned old = atomicAdd(&d_barCnt, 1);
        if (old == (NCTA - 1u)) {
            d_barCnt = 0;
            __threadfence();
            atomicExch(&d_barGen, g + 1u);
        } else {
            unsigned spins = 0;
            while (*genp == g && spins < (1u << 26)) spins++;
        }
        __threadfence();
    }
    __syncthreads();
}

// ---------------- prep kernels ----------------
__global__ void __launch_bounds__(256) rownorm_kernel(const float* __restrict__ A) {
    int n = blockIdx.x;
    const float* row = A + (size_t)n * NN;
    float s = 0.f;
    for (int j = threadIdx.x; j < NN; j += 256) s += row[j];
    __shared__ float red[256];
    red[threadIdx.x] = s;
    __syncthreads();
    for (int o = 128; o > 0; o >>= 1) {
        if (threadIdx.x < o) red[threadIdx.x] += red[threadIdx.x + o];
        __syncthreads();
    }
    float D = red[0];
    float Dinv = (D > 0.f) ? (1.0f / D) : 0.f;
    if (threadIdx.x == 0) d_Dfac[n] = D / (D + 1e-8f);
    __half* dst = d_Ah + (size_t)n * NN;
    for (int j = threadIdx.x; j < NN; j += 256) dst[j] = __float2half(row[j] * Dinv);
}

__global__ void __launch_bounds__(256) build_u_kernel(const float* __restrict__ m,
                                                      const float* __restrict__ tf,
                                                      const float* __restrict__ tj) {
    int i = blockIdx.x * 256 + threadIdx.x;
    if (i >= NN * 256) return;
    int n = i >> 8, c = i & 255;
    float v = 0.f;
    if (c < 64)        v = m[n * 64 + c];
    else if (c < 128)  v = tf[n * 64 + c - 64];
    else if (c < 192)  v = tj[n * 64 + c - 128];
    d_U16[i] = __float2half(v);
}

// W_msg layout [4][3][131][128]: ((p*3+k)*131 + d)*128 + j
__global__ void __launch_bounds__(256) build_w_kernel(const float* __restrict__ W_msg,
                                                      const float* __restrict__ W_ih,
                                                      const float* __restrict__ W_hh) {
    int i = blockIdx.x * 256 + threadIdx.x;
    const int NWCAT = 384 * 512;
    const int NWUC  = 3 * 3 * 4 * 128;
    const int NWBLK = 256 * 768;
    if (i < NWCAT) {
        int d = i >> 9, q = i & 511;
        int p = q >> 7, j = q & 127;
        int kc = d >> 7, c = d & 127;
        float v;
        if (kc == 0)      v = W_msg[((p*3+0)*DIN_ + c)*128 + j] - W_msg[((p*3+2)*DIN_ + c)*128 + j];
        else if (kc == 1) v = W_msg[((p*3+1)*DIN_ + c)*128 + j];
        else              v = 2.f * W_msg[((p*3+2)*DIN_ + c)*128 + j];
        d_Wcat[i] = __float2half(v);
    } else if (i < NWCAT + NWUC) {
        int r = i - NWCAT;
        int j = r & 127;
        int p = (r >> 7) & 3;
        int t2 = r >> 9;          // 0..8 = c*3 + which
        int which = t2 % 3;
        int c = t2 / 3;
        int dd = 128 + c;
        float v;
        if (which == 0)      v = W_msg[((p*3+0)*DIN_ + dd)*128 + j] - W_msg[((p*3+2)*DIN_ + dd)*128 + j];
        else if (which == 1) v = W_msg[((p*3+1)*DIN_ + dd)*128 + j];
        else                 v = 2.f * W_msg[((p*3+2)*DIN_ + dd)*128 + j];
        d_WuC[r] = v;
    } else if (i < NWCAT + NWUC + NWBLK) {
        int r = i - (NWCAT + NWUC);
        int d = r / 768, c = r - d * 768;
        float v = 0.f;
        if (d < 128) {
            if (c < 384) v = W_ih[(size_t)c * GIN_ + d];
        } else {
            if (c >= 384) v = W_hh[(size_t)(c - 384) * 128 + (d - 128)];
        }
        d_Wblk[r] = __float2half(v);
    }
}

__global__ void __launch_bounds__(256) init_kernel() {
    int i = blockIdx.x * 256 + threadIdx.x;
    if (i >= NN * 128) return;
    int n = i >> 7, j = i & 127;
    d_hst[i] = 0.f;
    d_S[n * 384 + j] = __float2half(0.f);
    d_X[n * 256 + 128 + j] = __float2half(0.f);
    if (i < NN * 4) d_logit[i] = 0.f;
}

// ---------------- standalone 2-stage HMMA GEMM, fp16 out: C = A @ B -------------
__global__ void __launch_bounds__(256) gemmH(const __half* __restrict__ Ag, int lda,
                                             const __half* __restrict__ Bg, int ldb,
                                             __half* __restrict__ Cg, int ldc, int K) {
    __shared__ __half sA[2][128][40];
    __shared__ __half sB[2][32][136];
    const int tid = threadIdx.x;
    const int lane = tid & 31, w = tid >> 5;
    const int wm = w >> 1, wn = w & 1;
    const int g = lane >> 2, tig = lane & 3;
    const int lm = lane & 15, hi = lane >> 4;
    const int row0 = blockIdx.y * 128;
    const int col0 = blockIdx.x * 128;
    const int NIT = K / 32;

    uint32_t sAb = (uint32_t)__cvta_generic_to_shared(&sA[0][0][0]);
    uint32_t sBb = (uint32_t)__cvta_generic_to_shared(&sB[0][0][0]);

    float acc[2][8][4];
#pragma unroll
    for (int a = 0; a < 2; a++)
#pragma unroll
        for (int b = 0; b < 8; b++)
#pragma unroll
            for (int c = 0; c < 4; c++) acc[a][b][c] = 0.f;

    auto load_stage = [&](int s, int it) {
        int kg = it * 32;
        uint32_t aS = sAb + s * 10240;
        uint32_t bS = sBb + s * 8704;
#pragma unroll
        for (int ch = tid; ch < 512; ch += 256) {
            int r = ch >> 2, c = (ch & 3) << 3;
            CPA16(aS + (uint32_t)(r * 40 + c) * 2, Ag + (size_t)(row0 + r) * lda + kg + c);
        }
#pragma unroll
        for (int ch = tid; ch < 512; ch += 256) {
            int r = ch >> 4, c = (ch & 15) << 3;
            CPA16(bS + (uint32_t)(r * 136 + c) * 2, Bg + (size_t)(kg + r) * ldb + col0 + c);
        }
    };

    load_stage(0, 0);
    CPCOMMIT();

    for (int it = 0; it < NIT; it++) {
        if (it + 1 < NIT) {
            load_stage((it + 1) & 1, it + 1);
            CPCOMMIT();
            asm volatile("cp.async.wait_group 1;\n" ::);
        } else {
            asm volatile("cp.async.wait_group 0;\n" ::);
        }
        __syncthreads();

        int s = it & 1;
        uint32_t aS = sAb + s * 10240;
        uint32_t bS = sBb + s * 8704;
#pragma unroll
        for (int ks = 0; ks < 2; ks++) {
            int kk = ks * 16;
            uint32_t Af[2][4];
#pragma unroll
            for (int ms = 0; ms < 2; ms++) {
                int rm = wm * 32 + ms * 16;
                uint32_t addr = aS + (uint32_t)((rm + lm) * 40 + kk + hi * 8) * 2;
                asm volatile("ldmatrix.sync.aligned.m8n8.x4.shared.b16 {%0,%1,%2,%3},[%4];\n"
                             : "=r"(Af[ms][0]), "=r"(Af[ms][1]), "=r"(Af[ms][2]), "=r"(Af[ms][3])
                             : "r"(addr));
            }
            uint32_t Bf[8][2];
#pragma unroll
            for (int nb = 0; nb < 4; nb++) {
                int cn = wn * 64 + nb * 16;
                uint32_t r0, r1, r2, r3;
                uint32_t addr = bS + (uint32_t)((kk + lm) * 136 + cn + hi * 8) * 2;
                asm volatile("ldmatrix.sync.aligned.m8n8.x4.trans.shared.b16 {%0,%1,%2,%3},[%4];\n"
                             : "=r"(r0), "=r"(r1), "=r"(r2), "=r"(r3) : "r"(addr));
                Bf[2*nb][0] = r0; Bf[2*nb][1] = r1;
                Bf[2*nb+1][0] = r2; Bf[2*nb+1][1] = r3;
            }
#pragma unroll
            for (int ms = 0; ms < 2; ms++)
#pragma unroll
                for (int ns = 0; ns < 8; ns++)
                    asm volatile(
                        "mma.sync.aligned.m16n8k16.row.col.f32.f16.f16.f32 "
                        "{%0,%1,%2,%3},{%4,%5,%6,%7},{%8,%9},{%0,%1,%2,%3};\n"
                        : "+f"(acc[ms][ns][0]), "+f"(acc[ms][ns][1]),
                          "+f"(acc[ms][ns][2]), "+f"(acc[ms][ns][3])
                        : "r"(Af[ms][0]), "r"(Af[ms][1]), "r"(Af[ms][2]), "r"(Af[ms][3]),
                          "r"(Bf[ns][0]), "r"(Bf[ns][1]));
        }
        __syncthreads();
    }

#pragma unroll
    for (int ms = 0; ms < 2; ms++) {
        int r = row0 + wm * 32 + ms * 16 + g;
#pragma unroll
        for (int ns = 0; ns < 8; ns++) {
            int c = col0 + wn * 64 + ns * 8 + tig * 2;
            Cg[(size_t)r * ldc + c]           = __float2half(acc[ms][ns][0]);
            Cg[(size_t)r * ldc + c + 1]       = __float2half(acc[ms][ns][1]);
            Cg[(size_t)(r + 8) * ldc + c]     = __float2half(acc[ms][ns][2]);
            Cg[(size_t)(r + 8) * ldc + c + 1] = __float2half(acc[ms][ns][3]);
        }
    }
}

// ---------------- in-kernel 32-K gemm phase (fp32 out) --------------------------
__device__ __forceinline__ void gemm32(const __half* __restrict__ Ag, int lda,
                                       const __half* __restrict__ Bg, int ldb,
                                       float* __restrict__ Cg, int ldc, int K,
                                       int row0, int col0, uint32_t base, int tid) {
    const int lane = tid & 31, w = tid >> 5;
    const int wm = w >> 1, wn = w & 1;
    const int g = lane >> 2, tig = lane & 3;
    const int lm = lane & 15, hi = lane >> 4;
    const int NIT = K / 32;
    uint32_t sAb = base;
    uint32_t sBb = base + 20480;

    float acc[2][8][4];
#pragma unroll
    for (int a = 0; a < 2; a++)
#pragma unroll
        for (int b = 0; b < 8; b++)
#pragma unroll
            for (int c = 0; c < 4; c++) acc[a][b][c] = 0.f;

    auto load_stage = [&](int s, int it) {
        int kg = it * 32;
        uint32_t aS = sAb + s * 10240;
        uint32_t bS = sBb + s * 8704;
#pragma unroll
        for (int ch = tid; ch < 512; ch += 256) {
            int r = ch >> 2, c = (ch & 3) << 3;
            CPA16(aS + (uint32_t)(r * 40 + c) * 2, Ag + (size_t)(row0 + r) * lda + kg + c);
        }
#pragma unroll
        for (int ch = tid; ch < 512; ch += 256) {
            int r = ch >> 4, c = (ch & 15) << 3;
            CPA16(bS + (uint32_t)(r * 136 + c) * 2, Bg + (size_t)(kg + r) * ldb + col0 + c);
        }
    };

    load_stage(0, 0);
    CPCOMMIT();

    for (int it = 0; it < NIT; it++) {
        if (it + 1 < NIT) {
            load_stage((it + 1) & 1, it + 1);
            CPCOMMIT();
            asm volatile("cp.async.wait_group 1;\n" ::);
        } else {
            asm volatile("cp.async.wait_group 0;\n" ::);
        }
        __syncthreads();

        int s = it & 1;
        uint32_t aS = sAb + s * 10240;
        uint32_t bS = sBb + s * 8704;
#pragma unroll
        for (int ks = 0; ks < 2; ks++) {
            int kk = ks * 16;
            uint32_t Af[2][4];
#pragma unroll
            for (int ms = 0; ms < 2; ms++) {
                int rm = wm * 32 + ms * 16;
                uint32_t addr = aS + (uint32_t)((rm + lm) * 40 + kk + hi * 8) * 2;
                asm volatile("ldmatrix.sync.aligned.m8n8.x4.shared.b16 {%0,%1,%2,%3},[%4];\n"
                             : "=r"(Af[ms][0]), "=r"(Af[ms][1]), "=r"(Af[ms][2]), "=r"(Af[ms][3])
                             : "r"(addr));
            }
            uint32_t Bf[8][2];
#pragma unroll
            for (int nb = 0; nb < 4; nb++) {
                int cn = wn * 64 + nb * 16;
                uint32_t r0, r1, r2, r3;
                uint32_t addr = bS + (uint32_t)((kk + lm) * 136 + cn + hi * 8) * 2;
                asm volatile("ldmatrix.sync.aligned.m8n8.x4.trans.shared.b16 {%0,%1,%2,%3},[%4];\n"
                             : "=r"(r0), "=r"(r1), "=r"(r2), "=r"(r3) : "r"(addr));
                Bf[2*nb][0] = r0; Bf[2*nb][1] = r1;
                Bf[2*nb+1][0] = r2; Bf[2*nb+1][1] = r3;
            }
#pragma unroll
            for (int ms = 0; ms < 2; ms++)
#pragma unroll
                for (int ns = 0; ns < 8; ns++)
                    asm volatile(
                        "mma.sync.aligned.m16n8k16.row.col.f32.f16.f16.f32 "
                        "{%0,%1,%2,%3},{%4,%5,%6,%7},{%8,%9},{%0,%1,%2,%3};\n"
                        : "+f"(acc[ms][ns][0]), "+f"(acc[ms][ns][1]),
                          "+f"(acc[ms][ns][2]), "+f"(acc[ms][ns][3])
                        : "r"(Af[ms][0]), "r"(Af[ms][1]), "r"(Af[ms][2]), "r"(Af[ms][3]),
                          "r"(Bf[ns][0]), "r"(Bf[ns][1]));
        }
        __syncthreads();
    }

#pragma unroll
    for (int ms = 0; ms < 2; ms++) {
        int r = row0 + wm * 32 + ms * 16 + g;
#pragma unroll
        for (int ns = 0; ns < 8; ns++) {
            int c = col0 + wn * 64 + ns * 8 + tig * 2;
            *(float2*)&Cg[(size_t)r * ldc + c]       = make_float2(acc[ms][ns][0], acc[ms][ns][1]);
            *(float2*)&Cg[(size_t)(r + 8) * ldc + c] = make_float2(acc[ms][ns][2], acc[ms][ns][3]);
        }
    }
}

// ---------------- in-kernel diffusion tile (BK=64, K=1024, partials) ------------
__device__ __forceinline__ void diff_tile(const __half* __restrict__ Apt,
                                          int row0, int kbase, int colOff,
                                          float* __restrict__ Pz,
                                          uint32_t base, int tid) {
    const int lane = tid & 31, w = tid >> 5;
    const int wm = w >> 1, wn = w & 1;
    const int g = lane >> 2, tig = lane & 3;
    const int lm = lane & 15, hi = lane >> 4;
    uint32_t sAb = base;
    uint32_t sBb = base + 2 * A_ST;

    float acc[2][8][4];
#pragma unroll
    for (int a = 0; a < 2; a++)
#pragma unroll
        for (int b = 0; b < 8; b++)
#pragma unroll
            for (int c = 0; c < 4; c++) acc[a][b][c] = 0.f;

    auto load_stage = [&](int s, int it) {
        int kg = kbase + it * 64;
        uint32_t aS = sAb + s * A_ST;
        uint32_t bS = sBb + s * B_ST;
#pragma unroll
        for (int ch = tid; ch < 1024; ch += 256) {
            int r = ch >> 3, c = (ch & 7) << 3;
            CPA16(aS + (uint32_t)(r * 72 + c) * 2, Apt + (size_t)(row0 + r) * NN + kg + c);
        }
#pragma unroll
        for (int ch = tid; ch < 1024; ch += 256) {
            int r = ch >> 4, c = (ch & 15) << 3;
            CPA16(bS + (uint32_t)(r * 136 + c) * 2, d_S + (size_t)(kg + r) * 384 + c);
        }
    };

    load_stage(0, 0);
    CPCOMMIT();

    const int NIT = 16;
    for (int it = 0; it < NIT; it++) {
        if (it + 1 < NIT) {
            load_stage((it + 1) & 1, it + 1);
            CPCOMMIT();
            asm volatile("cp.async.wait_group 1;\n" ::);
        } else {
            asm volatile("cp.async.wait_group 0;\n" ::);
        }
        __syncthreads();

        int s = it & 1;
        uint32_t aS = sAb + s * A_ST;
        uint32_t bS = sBb + s * B_ST;
#pragma unroll
        for (int ks = 0; ks < 4; ks++) {
            int kk = ks * 16;
            uint32_t Af[2][4];
#pragma unroll
            for (int ms = 0; ms < 2; ms++) {
                int rm = wm * 32 + ms * 16;
                uint32_t addr = aS + (uint32_t)((rm + lm) * 72 + kk + hi * 8) * 2;
                asm volatile("ldmatrix.sync.aligned.m8n8.x4.shared.b16 {%0,%1,%2,%3},[%4];\n"
                             : "=r"(Af[ms][0]), "=r"(Af[ms][1]), "=r"(Af[ms][2]), "=r"(Af[ms][3])
                             : "r"(addr));
            }
            uint32_t Bf[8][2];
#pragma unroll
            for (int nb = 0; nb < 4; nb++) {
                int cn = wn * 64 + nb * 16;
                uint32_t r0, r1, r2, r3;
                uint32_t addr = bS + (uint32_t)((kk + lm) * 136 + cn + hi * 8) * 2;
                asm volatile("ldmatrix.sync.aligned.m8n8.x4.trans.shared.b16 {%0,%1,%2,%3},[%4];\n"
                             : "=r"(r0), "=r"(r1), "=r"(r2), "=r"(r3) : "r"(addr));
                Bf[2*nb][0] = r0; Bf[2*nb][1] = r1;
                Bf[2*nb+1][0] = r2; Bf[2*nb+1][1] = r3;
            }
#pragma unroll
            for (int ms = 0; ms < 2; ms++)
#pragma unroll
                for (int ns = 0; ns < 8; ns++)
                    asm volatile(
                        "mma.sync.aligned.m16n8k16.row.col.f32.f16.f16.f32 "
                        "{%0,%1,%2,%3},{%4,%5,%6,%7},{%8,%9},{%0,%1,%2,%3};\n"
                        : "+f"(acc[ms][ns][0]), "+f"(acc[ms][ns][1]),
                          "+f"(acc[ms][ns][2]), "+f"(acc[ms][ns][3])
                        : "r"(Af[ms][0]), "r"(Af[ms][1]), "r"(Af[ms][2]), "r"(Af[ms][3]),
                          "r"(Bf[ns][0]), "r"(Bf[ns][1]));
        }
        __syncthreads();
    }

#pragma unroll
    for (int ms = 0; ms < 2; ms++) {
        int r = row0 + wm * 32 + ms * 16 + g;
#pragma unroll
        for (int ns = 0; ns < 8; ns++) {
            int c = colOff + wn * 64 + ns * 8 + tig * 2;
            *(float2*)&Pz[(size_t)r * 256 + c]       = make_float2(acc[ms][ns][0], acc[ms][ns][1]);
            *(float2*)&Pz[(size_t)(r + 8) * 256 + c] = make_float2(acc[ms][ns][2], acc[ms][ns][3]);
        }
    }
}

// ---------------- persistent mega-kernel: all 64 steps --------------------------
__global__ void __launch_bounds__(256, 2) megastep(
        const float* __restrict__ x_seq, const float* __restrict__ m_seq,
        const float* __restrict__ tf_seq, const float* __restrict__ tj_seq,
        const float* __restrict__ b_msg, const float* __restrict__ mix_b,
        const float* __restrict__ path_bias, const float* __restrict__ W_ih,
        const float* __restrict__ b_ih, const float* __restrict__ b_hh,
        const float* __restrict__ out_W, const float* __restrict__ out_b,
        const float* __restrict__ mix_W, float* __restrict__ out) {
    extern __shared__ __half dsm[];
    __shared__ float sred[2][4][5];
    const int tid = threadIdx.x;
    const int cta = blockIdx.x;
    uint32_t base = (uint32_t)__cvta_generic_to_shared(dsm);
    const size_t slab = (size_t)NN * 256;

    for (int t = 0; t < TT; t++) {
        // ---- Phase D: [G1|G2] partials.  cta = bz*64 + g*32 + by ----
        {
            int bz = cta >> 6;
            int g  = (cta >> 5) & 1;
            int by = cta & 31;
            const __half* Apt = g ? d_A2 : d_Ah;
            diff_tile(Apt, by * 128, bz * 1024, g * 128, d_Part + (size_t)bz * slab, base, tid);
        }
        gridbar();

        // ---- Phase R: reduce 4 slabs -> S cols 128..383 (fp16) ----
        {
#pragma unroll
            for (int k = 0; k < 4; k++) {
                size_t e = (size_t)cta * 4096 + (size_t)(k * 256 + tid) * 4;
                int n = (int)(e >> 8);
                int c = (int)(e & 255);
                const float* p = d_Part + (size_t)n * 256 + c;
                float4 s0 = ldcg4(p);
                float4 s1 = ldcg4(p + slab);
                float4 s2 = ldcg4(p + 2 * slab);
                float4 s3 = ldcg4(p + 3 * slab);
                float x0 = s0.x + s1.x + s2.x + s3.x;
                float x1 = s0.y + s1.y + s2.y + s3.y;
                float x2 = s0.z + s1.z + s2.z + s3.z;
                float x3 = s0.w + s1.w + s2.w + s3.w;
                __half* o = d_S + (size_t)n * 384 + 128 + c;
                *(__half2*)o       = __floats2half2_rn(x0, x1);
                *(__half2*)(o + 2) = __floats2half2_rn(x2, x3);
            }
        }
        gridbar();

        // ---- Phase M4: M4 = S @ Wcat  (tiles 4 x 32 = 128) ----
        if (cta < 128) {
            gemm32(d_S, 384, d_Wcat, 512, d_M4, 512, 384,
                   (cta >> 2) * 128, (cta & 3) * 128, base, tid);
        }
        gridbar();

        // ---- Phase MSG: softmax-mix + tanh -> X[:,0:128] ----
        {
#pragma unroll
            for (int chunk = 0; chunk < 8; chunk++) {
                int idx = cta * 2048 + chunk * 256 + tid;
                int n = idx >> 7, j = idx & 127;
                float lg[4];
#pragma unroll
                for (int p = 0; p < 4; p++)
                    lg[p] = ldcg(d_logit + n * 4 + p) + mix_b[p] + path_bias[p];
                float mx = fmaxf(fmaxf(lg[0], lg[1]), fmaxf(lg[2], lg[3]));
                float e0 = expf(lg[0]-mx), e1 = expf(lg[1]-mx), e2 = expf(lg[2]-mx), e3 = expf(lg[3]-mx);
                float inv = 1.f / (e0 + e1 + e2 + e3);
                float wp[4] = {e0*inv, e1*inv, e2*inv, e3*inv};

                float u[3], p1c[3], p2c[3];
                u[0] = m_seq[n * TT + t];
                u[1] = tf_seq[n * TT + t];
                u[2] = tj_seq[n * TT + t];
#pragma unroll
                for (int c = 0; c < 3; c++) {
                    p1c[c] = __half2float(d_P1[n * 256 + c * 64 + t]);
                    p2c[c] = __half2float(d_P2[n * 256 + c * 64 + t]);
                }
                float msg = 0.f;
#pragma unroll
                for (int p = 0; p < 4; p++) {
                    float a = ldcg(d_M4 + (size_t)n * 512 + p * 128 + j) + b_msg[p * 128 + j];
#pragma unroll
                    for (int c = 0; c < 3; c++) {
                        a += u[c]   * d_WuC[((c * 3 + 0) * 4 + p) * 128 + j];
                        a += p1c[c] * d_WuC[((c * 3 + 1) * 4 + p) * 128 + j];
                        a += p2c[c] * d_WuC[((c * 3 + 2) * 4 + p) * 128 + j];
                    }
                    msg += wp[p] * tanhf(a);
                }
                d_X[(size_t)n * 256 + j] = __float2half(msg);
            }
        }
        gridbar();

        // ---- Phase GG: GG = X @ Wblk (tiles 6 x 32 = 192) ----
        if (cta < 192) {
            int q = cta % 6, r = cta / 6;
            gemm32(d_X, 256, d_Wblk, 768, d_GG, 768, 256,
                   r * 128, q * 128, base, tid);
        }
        gridbar();

        // ---- Phase GRU: gates + h update + pred + next logits ----
        {
            int j = tid & 127, nl = tid >> 7;
#pragma unroll
            for (int pass = 0; pass < 8; pass++) {
                int n = cta * 16 + pass * 2 + nl;
                float x = x_seq[n * TT + t];
                float m = m_seq[n * TT + t];
                float tfv = tf_seq[n * TT + t];
                float tjv = tj_seq[n * TT + t];
                float h = d_hst[n * 128 + j];

                const float* ggn = d_GG + (size_t)n * 768;
                float gi[3], gh[3];
#pragma unroll
                for (int q = 0; q < 3; q++) {
                    int r = q * 128 + j;
                    const float* wr = W_ih + (size_t)r * GIN_ + 128;
                    gi[q] = ldcg(ggn + r) + x * wr[0] + m * wr[1] + tfv * wr[2] + tjv * wr[3] + b_ih[r];
                    gh[q] = ldcg(ggn + 384 + r) + b_hh[r];
                }
                float rg = 1.f / (1.f + expf(-(gi[0] + gh[0])));
                float z  = 1.f / (1.f + expf(-(gi[1] + gh[1])));
                float nc = tanhf(gi[2] + rg * gh[2]);
                float hn = (1.f - z) * nc + z * h;
                float mp = __half2float(d_P1[n * 256 + t]) * d_Dfac[n];
                float skip = (0.1f + 0.05f * (1.f - m)) * (1.f - 0.3f * mp);
                float h2 = hn + skip * h;

                d_hst[n * 128 + j] = h2;
                __half hh = __float2half(h2);
                d_S[(size_t)n * 384 + j] = hh;
                d_X[(size_t)n * 256 + 128 + j] = hh;

                // 5 reductions over j: pred, 4 logits
                float v[5];
                v[0] = h2 * out_W[j];
#pragma unroll
                for (int p = 0; p < 4; p++) v[p + 1] = h2 * mix_W[p * 128 + j];
#pragma unroll
                for (int q = 0; q < 5; q++) {
                    float s = v[q];
#pragma unroll
                    for (int o = 16; o > 0; o >>= 1)
                        s += __shfl_down_sync(0xFFFFFFFFu, s, o);
                    if ((j & 31) == 0) sred[nl][j >> 5][q] = s;
                }
                __syncthreads();
                if (j == 0) {
                    float pr = sred[nl][0][0] + sred[nl][1][0] + sred[nl][2][0] + sred[nl][3][0];
                    out[n * TT + t] = pr + out_b[0];
#pragma unroll
                    for (int p = 0; p < 4; p++)
                        d_logit[n * 4 + p] = sred[nl][0][p+1] + sred[nl][1][p+1]
                                           + sred[nl][2][p+1] + sred[nl][3][p+1];
                }
                __syncthreads();
            }
        }
        gridbar();
    }
}

// ---------------- host launcher ----------------
extern "C" void kernel_launch(void* const* d_in, const int* in_sizes, int n_in,
                              void* d_out, int out_size) {
    const float* x_seq     = (const float*)d_in[0];
    const float* m_seq     = (const float*)d_in[1];
    const float* tf_seq    = (const float*)d_in[2];
    const float* tj_seq    = (const float*)d_in[3];
    const float* A         = (const float*)d_in[4];
    const float* W_msg     = (const float*)d_in[5];
    const float* b_msg     = (const float*)d_in[6];
    const float* path_bias = (const float*)d_in[7];
    const float* mix_W     = (const float*)d_in[8];
    const float* mix_b     = (const float*)d_in[9];
    const float* W_ih      = (const float*)d_in[10];
    const float* W_hh      = (const float*)d_in[11];
    const float* b_ih      = (const float*)d_in[12];
    const float* b_hh      = (const float*)d_in[13];
    const float* out_W     = (const float*)d_in[14];
    const float* out_b     = (const float*)d_in[15];
    float* out = (float*)d_out;

    void *pAh, *pA2, *pU, *pP1, *pP2;
    cudaGetSymbolAddress(&pAh, d_Ah);
    cudaGetSymbolAddress(&pA2, d_A2);
    cudaGetSymbolAddress(&pU, d_U16);
    cudaGetSymbolAddress(&pP1, d_P1);
    cudaGetSymbolAddress(&pP2, d_P2);

    cudaFuncSetAttribute(megastep, cudaFuncAttributeMaxDynamicSharedMemorySize, DSM_BYTES);

    build_u_kernel<<<(NN * 256 + 255) / 256, 256>>>(m_seq, tf_seq, tj_seq);
    build_w_kernel<<<(384*512 + 3*3*4*128 + 256*768 + 255) / 256, 256>>>(W_msg, W_ih, W_hh);
    rownorm_kernel<<<NN, 256>>>(A);
    // A2 = Anorm @ Anorm (one-time, fp16)
    gemmH<<<dim3(32, 32), 256>>>((const __half*)pAh, NN, (const __half*)pAh, NN,
                                 (__half*)pA2, NN, NN);
    // P1 = Anorm @ U ; P2 = A2 @ U (independent)
    gemmH<<<dim3(2, 32), 256>>>((const __half*)pAh, NN, (const __half*)pU, 256,
                                (__half*)pP1, 256, NN);
    gemmH<<<dim3(2, 32), 256>>>((const __half*)pA2, NN, (const __half*)pU, 256,
                                (__half*)pP2, 256, NN);
    init_kernel<<<(NN * 128 + 255) / 256, 256>>>();

    // all 64 steps in one persistent kernel
    megastep<<<NCTA, 256, DSM_BYTES>>>(x_seq, m_seq, tf_seq, tj_seq, b_msg, mix_b,
                                       path_bias, W_ih, b_ih, b_hh, out_W, out_b,
                                       mix_W, out);
}

// round 17
// speedup vs baseline: 1.0398x; 1.0398x over previous
#include <cuda_runtime.h>
#include <cuda_fp16.h>
#include <cstdint>

#define NN 4096
#define TT 64
#define DIN_ 131
#define GIN_ 132
#define NCTA 256
#define A_ST 18432              // diffusion A stage: 128 x 72 halves
#define B_ST 17408              // diffusion B stage: 64 x 136 halves
#define DSM_BYTES (2 * (A_ST + B_ST))   // 71680 (2-stage, PROVEN 2 CTA/SM)

// ---------------- static device workspace ----------------
__device__ __half d_Ah[(size_t)NN * NN];      // row-normalized A fp16
__device__ __half d_A2[(size_t)NN * NN];      // Anorm^2 fp16
__device__ float  d_Dfac[NN];                 // D/(D+1e-8)
__device__ __half d_U16[NN * 256];            // [n][c*64+t] c=m,tf,tj
__device__ __half d_P1[NN * 256];             // Anorm @ U
__device__ __half d_P2[NN * 256];             // Anorm^2 @ U
__device__ __half d_S[NN * 384];              // [h | G1 | G2]
__device__ __half d_X[NN * 256];              // [msg | h]
__device__ float  d_hst[NN * 128];            // carried state fp32
__device__ float  d_logit[NN * 4];            // h @ mixW^T (raw, prev step)
__device__ float  d_GG[(size_t)NN * 768];     // [gi_msg | gh]
__device__ float  d_Part[(size_t)4 * NN * 256]; // D partials / M4 partials (16.8 MB)
__device__ __half d_Wcat[384 * 512];          // folded Cheb weights
__device__ float  d_WuC[3 * 3 * 4 * 128];     // folded Cheb weights (u part)
__device__ __half d_Wblk[256 * 768];          // block-diag [Wihm ; Whh]
__device__ unsigned d_barCnt;
__device__ unsigned d_barGen;

#define CPA16(dst, src) asm volatile("cp.async.cg.shared.global [%0], [%1], 16;\n" :: "r"(dst), "l"(src))
#define CPCOMMIT() asm volatile("cp.async.commit_group;\n" ::)

__device__ __forceinline__ float ldcg(const float* p) {
    float v;
    asm volatile("ld.global.cg.f32 %0,[%1];" : "=f"(v) : "l"(p));
    return v;
}
__device__ __forceinline__ float4 ldcg4(const float* p) {
    float4 v;
    asm volatile("ld.global.cg.v4.f32 {%0,%1,%2,%3},[%4];"
                 : "=f"(v.x), "=f"(v.y), "=f"(v.z), "=f"(v.w) : "l"(p));
    return v;
}

// ---------------- bounded grid barrier (all 256 CTAs resident) ------------------
__device__ __forceinline__ void gridbar() {
    __syncthreads();
    if (threadIdx.x == 0) {
        __threadfence();
        volatile unsigned* genp = &d_barGen;
        unsigned g = *genp;
        unsigned old = atomicAdd(&d_barCnt, 1);
        if (old == (NCTA - 1u)) {
            d_barCnt = 0;
            __threadfence();
            atomicExch(&d_barGen, g + 1u);
        } else {
            unsigned spins = 0;
            while (*genp == g && spins < (1u << 26)) spins++;
        }
        __threadfence();
    }
    __syncthreads();
}

// ---------------- prep kernels ----------------
__global__ void __launch_bounds__(256) rownorm_kernel(const float* __restrict__ A) {
    int n = blockIdx.x;
    const float* row = A + (size_t)n * NN;
    float s = 0.f;
    for (int j = threadIdx.x; j < NN; j += 256) s += row[j];
    __shared__ float red[256];
    red[threadIdx.x] = s;
    __syncthreads();
    for (int o = 128; o > 0; o >>= 1) {
        if (threadIdx.x < o) red[threadIdx.x] += red[threadIdx.x + o];
        __syncthreads();
    }
    float D = red[0];
    float Dinv = (D > 0.f) ? (1.0f / D) : 0.f;
    if (threadIdx.x == 0) d_Dfac[n] = D / (D + 1e-8f);
    __half* dst = d_Ah + (size_t)n * NN;
    for (int j = threadIdx.x; j < NN; j += 256) dst[j] = __float2half(row[j] * Dinv);
}

__global__ void __launch_bounds__(256) build_u_kernel(const float* __restrict__ m,
                                                      const float* __restrict__ tf,
                                                      const float* __restrict__ tj) {
    int i = blockIdx.x * 256 + threadIdx.x;
    if (i >= NN * 256) return;
    int n = i >> 8, c = i & 255;
    float v = 0.f;
    if (c < 64)        v = m[n * 64 + c];
    else if (c < 128)  v = tf[n * 64 + c - 64];
    else if (c < 192)  v = tj[n * 64 + c - 128];
    d_U16[i] = __float2half(v);
}

// W_msg layout [4][3][131][128]: ((p*3+k)*131 + d)*128 + j
__global__ void __launch_bounds__(256) build_w_kernel(const float* __restrict__ W_msg,
                                                      const float* __restrict__ W_ih,
                                                      const float* __restrict__ W_hh) {
    int i = blockIdx.x * 256 + threadIdx.x;
    const int NWCAT = 384 * 512;
    const int NWUC  = 3 * 3 * 4 * 128;
    const int NWBLK = 256 * 768;
    if (i < NWCAT) {
        int d = i >> 9, q = i & 511;
        int p = q >> 7, j = q & 127;
        int kc = d >> 7, c = d & 127;
        float v;
        if (kc == 0)      v = W_msg[((p*3+0)*DIN_ + c)*128 + j] - W_msg[((p*3+2)*DIN_ + c)*128 + j];
        else if (kc == 1) v = W_msg[((p*3+1)*DIN_ + c)*128 + j];
        else              v = 2.f * W_msg[((p*3+2)*DIN_ + c)*128 + j];
        d_Wcat[i] = __float2half(v);
    } else if (i < NWCAT + NWUC) {
        int r = i - NWCAT;
        int j = r & 127;
        int p = (r >> 7) & 3;
        int t2 = r >> 9;          // 0..8 = c*3 + which
        int which = t2 % 3;
        int c = t2 / 3;
        int dd = 128 + c;
        float v;
        if (which == 0)      v = W_msg[((p*3+0)*DIN_ + dd)*128 + j] - W_msg[((p*3+2)*DIN_ + dd)*128 + j];
        else if (which == 1) v = W_msg[((p*3+1)*DIN_ + dd)*128 + j];
        else                 v = 2.f * W_msg[((p*3+2)*DIN_ + dd)*128 + j];
        d_WuC[r] = v;
    } else if (i < NWCAT + NWUC + NWBLK) {
        int r = i - (NWCAT + NWUC);
        int d = r / 768, c = r - d * 768;
        float v = 0.f;
        if (d < 128) {
            if (c < 384) v = W_ih[(size_t)c * GIN_ + d];
        } else {
            if (c >= 384) v = W_hh[(size_t)(c - 384) * 128 + (d - 128)];
        }
        d_Wblk[r] = __float2half(v);
    }
}

__global__ void __launch_bounds__(256) init_kernel() {
    int i = blockIdx.x * 256 + threadIdx.x;
    if (i >= NN * 128) return;
    int n = i >> 7, j = i & 127;
    d_hst[i] = 0.f;
    d_S[n * 384 + j] = __float2half(0.f);
    d_X[n * 256 + 128 + j] = __float2half(0.f);
    if (i < NN * 4) d_logit[i] = 0.f;
}

// ---------------- generic HMMA mainloop body ------------------------------------
__device__ __forceinline__ void hmma_body(const __half* __restrict__ Ag, int lda,
                                          const __half* __restrict__ Bg, int ldb,
                                          float acc[2][8][4], int K, int kbase,
                                          int row0, int col0, uint32_t sAb, uint32_t sBb,
                                          int tid) {
    const int lane = tid & 31, w = tid >> 5;
    const int wm = w >> 1, wn = w & 1;
    const int lm = lane & 15, hi = lane >> 4;
    const int NIT = K / 32;

    auto load_stage = [&](int s, int it) {
        int kg = kbase + it * 32;
        uint32_t aS = sAb + s * 10240;
        uint32_t bS = sBb + s * 8704;
#pragma unroll
        for (int ch = tid; ch < 512; ch += 256) {
            int r = ch >> 2, c = (ch & 3) << 3;
            CPA16(aS + (uint32_t)(r * 40 + c) * 2, Ag + (size_t)(row0 + r) * lda + kg + c);
        }
#pragma unroll
        for (int ch = tid; ch < 512; ch += 256) {
            int r = ch >> 4, c = (ch & 15) << 3;
            CPA16(bS + (uint32_t)(r * 136 + c) * 2, Bg + (size_t)(kg + r) * ldb + col0 + c);
        }
    };

    load_stage(0, 0);
    CPCOMMIT();

    for (int it = 0; it < NIT; it++) {
        if (it + 1 < NIT) {
            load_stage((it + 1) & 1, it + 1);
            CPCOMMIT();
            asm volatile("cp.async.wait_group 1;\n" ::);
        } else {
            asm volatile("cp.async.wait_group 0;\n" ::);
        }
        __syncthreads();

        int s = it & 1;
        uint32_t aS = sAb + s * 10240;
        uint32_t bS = sBb + s * 8704;
#pragma unroll
        for (int ks = 0; ks < 2; ks++) {
            int kk = ks * 16;
            uint32_t Af[2][4];
#pragma unroll
            for (int ms = 0; ms < 2; ms++) {
                int rm = wm * 32 + ms * 16;
                uint32_t addr = aS + (uint32_t)((rm + lm) * 40 + kk + hi * 8) * 2;
                asm volatile("ldmatrix.sync.aligned.m8n8.x4.shared.b16 {%0,%1,%2,%3},[%4];\n"
                             : "=r"(Af[ms][0]), "=r"(Af[ms][1]), "=r"(Af[ms][2]), "=r"(Af[ms][3])
                             : "r"(addr));
            }
            uint32_t Bf[8][2];
#pragma unroll
            for (int nb = 0; nb < 4; nb++) {
                int cn = wn * 64 + nb * 16;
                uint32_t r0, r1, r2, r3;
                uint32_t addr = bS + (uint32_t)((kk + lm) * 136 + cn + hi * 8) * 2;
                asm volatile("ldmatrix.sync.aligned.m8n8.x4.trans.shared.b16 {%0,%1,%2,%3},[%4];\n"
                             : "=r"(r0), "=r"(r1), "=r"(r2), "=r"(r3) : "r"(addr));
                Bf[2*nb][0] = r0; Bf[2*nb][1] = r1;
                Bf[2*nb+1][0] = r2; Bf[2*nb+1][1] = r3;
            }
#pragma unroll
            for (int ms = 0; ms < 2; ms++)
#pragma unroll
                for (int ns = 0; ns < 8; ns++)
                    asm volatile(
                        "mma.sync.aligned.m16n8k16.row.col.f32.f16.f16.f32 "
                        "{%0,%1,%2,%3},{%4,%5,%6,%7},{%8,%9},{%0,%1,%2,%3};\n"
                        : "+f"(acc[ms][ns][0]), "+f"(acc[ms][ns][1]),
                          "+f"(acc[ms][ns][2]), "+f"(acc[ms][ns][3])
                        : "r"(Af[ms][0]), "r"(Af[ms][1]), "r"(Af[ms][2]), "r"(Af[ms][3]),
                          "r"(Bf[ns][0]), "r"(Bf[ns][1]));
        }
        __syncthreads();
    }
}

// ---------------- standalone GEMM: A2 = Ah @ Ah (fp16 out) ----------------------
__global__ void __launch_bounds__(256) gemmA2() {
    __shared__ __half sA[2][128][40];
    __shared__ __half sB[2][32][136];
    const int tid = threadIdx.x;
    const int lane = tid & 31, w = tid >> 5;
    const int wm = w >> 1, wn = w & 1;
    const int g = lane >> 2, tig = lane & 3;
    const int row0 = blockIdx.y * 128, col0 = blockIdx.x * 128;
    float acc[2][8][4];
#pragma unroll
    for (int a = 0; a < 2; a++)
#pragma unroll
        for (int b = 0; b < 8; b++)
#pragma unroll
            for (int c = 0; c < 4; c++) acc[a][b][c] = 0.f;
    hmma_body(d_Ah, NN, d_Ah, NN, acc, NN, 0, row0, col0,
              (uint32_t)__cvta_generic_to_shared(&sA[0][0][0]),
              (uint32_t)__cvta_generic_to_shared(&sB[0][0][0]), tid);
#pragma unroll
    for (int ms = 0; ms < 2; ms++) {
        int r = row0 + wm * 32 + ms * 16 + g;
#pragma unroll
        for (int ns = 0; ns < 8; ns++) {
            int c = col0 + wn * 64 + ns * 8 + tig * 2;
            *(__half2*)&d_A2[(size_t)r * NN + c]       = __floats2half2_rn(acc[ms][ns][0], acc[ms][ns][1]);
            *(__half2*)&d_A2[(size_t)(r + 8) * NN + c] = __floats2half2_rn(acc[ms][ns][2], acc[ms][ns][3]);
        }
    }
}

// ---------------- standalone GEMM: P1 = Ah@U and P2 = A2@U (z selects) ----------
__global__ void __launch_bounds__(256) gemmP12() {
    __shared__ __half sA[2][128][40];
    __shared__ __half sB[2][32][136];
    const int tid = threadIdx.x;
    const int lane = tid & 31, w = tid >> 5;
    const int wm = w >> 1, wn = w & 1;
    const int g = lane >> 2, tig = lane & 3;
    const int row0 = blockIdx.y * 128, col0 = blockIdx.x * 128;
    const __half* Ag = blockIdx.z ? d_A2 : d_Ah;
    __half* Cg = blockIdx.z ? d_P2 : d_P1;
    float acc[2][8][4];
#pragma unroll
    for (int a = 0; a < 2; a++)
#pragma unroll
        for (int b = 0; b < 8; b++)
#pragma unroll
            for (int c = 0; c < 4; c++) acc[a][b][c] = 0.f;
    hmma_body(Ag, NN, d_U16, 256, acc, NN, 0, row0, col0,
              (uint32_t)__cvta_generic_to_shared(&sA[0][0][0]),
              (uint32_t)__cvta_generic_to_shared(&sB[0][0][0]), tid);
#pragma unroll
    for (int ms = 0; ms < 2; ms++) {
        int r = row0 + wm * 32 + ms * 16 + g;
#pragma unroll
        for (int ns = 0; ns < 8; ns++) {
            int c = col0 + wn * 64 + ns * 8 + tig * 2;
            *(__half2*)&Cg[(size_t)r * 256 + c]       = __floats2half2_rn(acc[ms][ns][0], acc[ms][ns][1]);
            *(__half2*)&Cg[(size_t)(r + 8) * 256 + c] = __floats2half2_rn(acc[ms][ns][2], acc[ms][ns][3]);
        }
    }
}

// ---------------- in-kernel gemm phase (fp32 out, with kbase) -------------------
__device__ __forceinline__ void gemm32(const __half* __restrict__ Ag, int lda,
                                       const __half* __restrict__ Bg, int ldb,
                                       float* __restrict__ Cg, int ldc, int K, int kbase,
                                       int row0, int col0, uint32_t base, int tid) {
    const int lane = tid & 31, w = tid >> 5;
    const int wm = w >> 1, wn = w & 1;
    const int g = lane >> 2, tig = lane & 3;
    float acc[2][8][4];
#pragma unroll
    for (int a = 0; a < 2; a++)
#pragma unroll
        for (int b = 0; b < 8; b++)
#pragma unroll
            for (int c = 0; c < 4; c++) acc[a][b][c] = 0.f;
    hmma_body(Ag, lda, Bg, ldb, acc, K, kbase, row0, col0, base, base + 20480, tid);
#pragma unroll
    for (int ms = 0; ms < 2; ms++) {
        int r = row0 + wm * 32 + ms * 16 + g;
#pragma unroll
        for (int ns = 0; ns < 8; ns++) {
            int c = col0 + wn * 64 + ns * 8 + tig * 2;
            *(float2*)&Cg[(size_t)r * ldc + c]       = make_float2(acc[ms][ns][0], acc[ms][ns][1]);
            *(float2*)&Cg[(size_t)(r + 8) * ldc + c] = make_float2(acc[ms][ns][2], acc[ms][ns][3]);
        }
    }
}

// ---------------- in-kernel diffusion tile (BK=64, K=1024, 2-stage, PROVEN) -----
__device__ __forceinline__ void diff_tile(const __half* __restrict__ Apt,
                                          int row0, int kbase, int colOff,
                                          float* __restrict__ Pz,
                                          uint32_t base, int tid) {
    const int lane = tid & 31, w = tid >> 5;
    const int wm = w >> 1, wn = w & 1;
    const int g = lane >> 2, tig = lane & 3;
    const int lm = lane & 15, hi = lane >> 4;
    uint32_t sAb = base;
    uint32_t sBb = base + 2 * A_ST;

    float acc[2][8][4];
#pragma unroll
    for (int a = 0; a < 2; a++)
#pragma unroll
        for (int b = 0; b < 8; b++)
#pragma unroll
            for (int c = 0; c < 4; c++) acc[a][b][c] = 0.f;

    auto load_stage = [&](int s, int it) {
        int kg = kbase + it * 64;
        uint32_t aS = sAb + s * A_ST;
        uint32_t bS = sBb + s * B_ST;
#pragma unroll
        for (int ch = tid; ch < 1024; ch += 256) {
            int r = ch >> 3, c = (ch & 7) << 3;
            CPA16(aS + (uint32_t)(r * 72 + c) * 2, Apt + (size_t)(row0 + r) * NN + kg + c);
        }
#pragma unroll
        for (int ch = tid; ch < 1024; ch += 256) {
            int r = ch >> 4, c = (ch & 15) << 3;
            CPA16(bS + (uint32_t)(r * 136 + c) * 2, d_S + (size_t)(kg + r) * 384 + c);
        }
    };

    load_stage(0, 0);
    CPCOMMIT();

    const int NIT = 16;
    for (int it = 0; it < NIT; it++) {
        if (it + 1 < NIT) {
            load_stage((it + 1) & 1, it + 1);
            CPCOMMIT();
            asm volatile("cp.async.wait_group 1;\n" ::);
        } else {
            asm volatile("cp.async.wait_group 0;\n" ::);
        }
        __syncthreads();

        int s = it & 1;
        uint32_t aS = sAb + s * A_ST;
        uint32_t bS = sBb + s * B_ST;
#pragma unroll
        for (int ks = 0; ks < 4; ks++) {
            int kk = ks * 16;
            uint32_t Af[2][4];
#pragma unroll
            for (int ms = 0; ms < 2; ms++) {
                int rm = wm * 32 + ms * 16;
                uint32_t addr = aS + (uint32_t)((rm + lm) * 72 + kk + hi * 8) * 2;
                asm volatile("ldmatrix.sync.aligned.m8n8.x4.shared.b16 {%0,%1,%2,%3},[%4];\n"
                             : "=r"(Af[ms][0]), "=r"(Af[ms][1]), "=r"(Af[ms][2]), "=r"(Af[ms][3])
                             : "r"(addr));
            }
            uint32_t Bf[8][2];
#pragma unroll
            for (int nb = 0; nb < 4; nb++) {
                int cn = wn * 64 + nb * 16;
                uint32_t r0, r1, r2, r3;
                uint32_t addr = bS + (uint32_t)((kk + lm) * 136 + cn + hi * 8) * 2;
                asm volatile("ldmatrix.sync.aligned.m8n8.x4.trans.shared.b16 {%0,%1,%2,%3},[%4];\n"
                             : "=r"(r0), "=r"(r1), "=r"(r2), "=r"(r3) : "r"(addr));
                Bf[2*nb][0] = r0; Bf[2*nb][1] = r1;
                Bf[2*nb+1][0] = r2; Bf[2*nb+1][1] = r3;
            }
#pragma unroll
            for (int ms = 0; ms < 2; ms++)
#pragma unroll
                for (int ns = 0; ns < 8; ns++)
                    asm volatile(
                        "mma.sync.aligned.m16n8k16.row.col.f32.f16.f16.f32 "
                        "{%0,%1,%2,%3},{%4,%5,%6,%7},{%8,%9},{%0,%1,%2,%3};\n"
                        : "+f"(acc[ms][ns][0]), "+f"(acc[ms][ns][1]),
                          "+f"(acc[ms][ns][2]), "+f"(acc[ms][ns][3])
                        : "r"(Af[ms][0]), "r"(Af[ms][1]), "r"(Af[ms][2]), "r"(Af[ms][3]),
                          "r"(Bf[ns][0]), "r"(Bf[ns][1]));
        }
        __syncthreads();
    }

#pragma unroll
    for (int ms = 0; ms < 2; ms++) {
        int r = row0 + wm * 32 + ms * 16 + g;
#pragma unroll
        for (int ns = 0; ns < 8; ns++) {
            int c = colOff + wn * 64 + ns * 8 + tig * 2;
            *(float2*)&Pz[(size_t)r * 256 + c]       = make_float2(acc[ms][ns][0], acc[ms][ns][1]);
            *(float2*)&Pz[(size_t)(r + 8) * 256 + c] = make_float2(acc[ms][ns][2], acc[ms][ns][3]);
        }
    }
}

// ---------------- persistent mega-kernel: all 64 steps --------------------------
__global__ void __launch_bounds__(256, 2) megastep(
        const float* __restrict__ x_seq, const float* __restrict__ m_seq,
        const float* __restrict__ tf_seq, const float* __restrict__ tj_seq,
        const float* __restrict__ b_msg, const float* __restrict__ mix_b,
        const float* __restrict__ path_bias, const float* __restrict__ W_ih,
        const float* __restrict__ b_ih, const float* __restrict__ b_hh,
        const float* __restrict__ out_W, const float* __restrict__ out_b,
        const float* __restrict__ mix_W, float* __restrict__ out) {
    extern __shared__ __half dsm[];
    __shared__ float sred[2][4][5];
    const int tid = threadIdx.x;
    const int cta = blockIdx.x;
    uint32_t base = (uint32_t)__cvta_generic_to_shared(dsm);
    const size_t slab = (size_t)NN * 256;
    const size_t mslab = (size_t)NN * 512;

    for (int t = 0; t < TT; t++) {
        // ---- Phase D: [G1|G2] partials.  cta = bz*64 + g*32 + by ----
        {
            int bz = cta >> 6;
            int g  = (cta >> 5) & 1;
            int by = cta & 31;
            const __half* Apt = g ? d_A2 : d_Ah;
            diff_tile(Apt, by * 128, bz * 1024, g * 128, d_Part + (size_t)bz * slab, base, tid);
        }
        gridbar();

        // ---- Phase R: reduce 4 slabs -> S cols 128..383 (fp16) ----
        {
#pragma unroll
            for (int k = 0; k < 4; k++) {
                size_t e = (size_t)cta * 4096 + (size_t)(k * 256 + tid) * 4;
                int n = (int)(e >> 8);
                int c = (int)(e & 255);
                const float* p = d_Part + (size_t)n * 256 + c;
                float4 s0 = ldcg4(p);
                float4 s1 = ldcg4(p + slab);
                float4 s2 = ldcg4(p + 2 * slab);
                float4 s3 = ldcg4(p + 3 * slab);
                float x0 = s0.x + s1.x + s2.x + s3.x;
                float x1 = s0.y + s1.y + s2.y + s3.y;
                float x2 = s0.z + s1.z + s2.z + s3.z;
                float x3 = s0.w + s1.w + s2.w + s3.w;
                __half* o = d_S + (size_t)n * 384 + 128 + c;
                *(__half2*)o       = __floats2half2_rn(x0, x1);
                *(__half2*)(o + 2) = __floats2half2_rn(x2, x3);
            }
        }
        gridbar();

        // ---- Phase M4: split-K2 partials = S @ Wcat (all 256 CTAs busy) ----
        {
            int s = cta >> 7;            // K half: 0 -> cols 0..191, 1 -> 192..383
            int tile = cta & 127;
            gemm32(d_S, 384, d_Wcat, 512,
                   d_Part + (size_t)s * mslab, 512, 192, s * 192,
                   (tile >> 2) * 128, (tile & 3) * 128, base, tid);
        }
        gridbar();

        // ---- Phase MSG: sum K-halves + softmax-mix + tanh -> X[:,0:128] ----
        {
#pragma unroll
            for (int chunk = 0; chunk < 8; chunk++) {
                int idx = cta * 2048 + chunk * 256 + tid;
                int n = idx >> 7, j = idx & 127;
                float lg[4];
#pragma unroll
                for (int p = 0; p < 4; p++)
                    lg[p] = ldcg(d_logit + n * 4 + p) + mix_b[p] + path_bias[p];
                float mx = fmaxf(fmaxf(lg[0], lg[1]), fmaxf(lg[2], lg[3]));
                float e0 = expf(lg[0]-mx), e1 = expf(lg[1]-mx), e2 = expf(lg[2]-mx), e3 = expf(lg[3]-mx);
                float inv = 1.f / (e0 + e1 + e2 + e3);
                float wp[4] = {e0*inv, e1*inv, e2*inv, e3*inv};

                float u[3], p1c[3], p2c[3];
                u[0] = m_seq[n * TT + t];
                u[1] = tf_seq[n * TT + t];
                u[2] = tj_seq[n * TT + t];
#pragma unroll
                for (int c = 0; c < 3; c++) {
                    p1c[c] = __half2float(d_P1[n * 256 + c * 64 + t]);
                    p2c[c] = __half2float(d_P2[n * 256 + c * 64 + t]);
                }
                float msg = 0.f;
#pragma unroll
                for (int p = 0; p < 4; p++) {
                    size_t off = (size_t)n * 512 + p * 128 + j;
                    float a = ldcg(d_Part + off) + ldcg(d_Part + mslab + off) + b_msg[p * 128 + j];
#pragma unroll
                    for (int c = 0; c < 3; c++) {
                        a += u[c]   * d_WuC[((c * 3 + 0) * 4 + p) * 128 + j];
                        a += p1c[c] * d_WuC[((c * 3 + 1) * 4 + p) * 128 + j];
                        a += p2c[c] * d_WuC[((c * 3 + 2) * 4 + p) * 128 + j];
                    }
                    msg += wp[p] * tanhf(a);
                }
                d_X[(size_t)n * 256 + j] = __float2half(msg);
            }
        }
        gridbar();

        // ---- Phase GG: GG = X @ Wblk (tiles 6 x 32 = 192) ----
        if (cta < 192) {
            int q = cta % 6, r = cta / 6;
            gemm32(d_X, 256, d_Wblk, 768, d_GG, 768, 256, 0,
                   r * 128, q * 128, base, tid);
        }
        gridbar();

        // ---- Phase GRU: gates + h update + pred + next logits ----
        {
            int j = tid & 127, nl = tid >> 7;
#pragma unroll
            for (int pass = 0; pass < 8; pass++) {
                int n = cta * 16 + pass * 2 + nl;
                float x = x_seq[n * TT + t];
                float m = m_seq[n * TT + t];
                float tfv = tf_seq[n * TT + t];
                float tjv = tj_seq[n * TT + t];
                float h = d_hst[n * 128 + j];

                const float* ggn = d_GG + (size_t)n * 768;
                float gi[3], gh[3];
#pragma unroll
                for (int q = 0; q < 3; q++) {
                    int r = q * 128 + j;
                    const float* wr = W_ih + (size_t)r * GIN_ + 128;
                    gi[q] = ldcg(ggn + r) + x * wr[0] + m * wr[1] + tfv * wr[2] + tjv * wr[3] + b_ih[r];
                    gh[q] = ldcg(ggn + 384 + r) + b_hh[r];
                }
                float rg = 1.f / (1.f + expf(-(gi[0] + gh[0])));
                float z  = 1.f / (1.f + expf(-(gi[1] + gh[1])));
                float nc = tanhf(gi[2] + rg * gh[2]);
                float hn = (1.f - z) * nc + z * h;
                float mp = __half2float(d_P1[n * 256 + t]) * d_Dfac[n];
                float skip = (0.1f + 0.05f * (1.f - m)) * (1.f - 0.3f * mp);
                float h2 = hn + skip * h;

                d_hst[n * 128 + j] = h2;
                __half hh = __float2half(h2);
                d_S[(size_t)n * 384 + j] = hh;
                d_X[(size_t)n * 256 + 128 + j] = hh;

                float v[5];
                v[0] = h2 * out_W[j];
#pragma unroll
                for (int p = 0; p < 4; p++) v[p + 1] = h2 * mix_W[p * 128 + j];
#pragma unroll
                for (int q = 0; q < 5; q++) {
                    float s = v[q];
#pragma unroll
                    for (int o = 16; o > 0; o >>= 1)
                        s += __shfl_down_sync(0xFFFFFFFFu, s, o);
                    if ((j & 31) == 0) sred[nl][j >> 5][q] = s;
                }
                __syncthreads();
                if (j == 0) {
                    float pr = sred[nl][0][0] + sred[nl][1][0] + sred[nl][2][0] + sred[nl][3][0];
                    out[n * TT + t] = pr + out_b[0];
#pragma unroll
                    for (int p = 0; p < 4; p++)
                        d_logit[n * 4 + p] = sred[nl][0][p+1] + sred[nl][1][p+1]
                                           + sred[nl][2][p+1] + sred[nl][3][p+1];
                }
                __syncthreads();
            }
        }
        gridbar();
    }
}

// ---------------- host launcher ----------------
extern "C" void kernel_launch(void* const* d_in, const int* in_sizes, int n_in,
                              void* d_out, int out_size) {
    const float* x_seq     = (const float*)d_in[0];
    const float* m_seq     = (const float*)d_in[1];
    const float* tf_seq    = (const float*)d_in[2];
    const float* tj_seq    = (const float*)d_in[3];
    const float* A         = (const float*)d_in[4];
    const float* W_msg     = (const float*)d_in[5];
    const float* b_msg     = (const float*)d_in[6];
    const float* path_bias = (const float*)d_in[7];
    const float* mix_W     = (const float*)d_in[8];
    const float* mix_b     = (const float*)d_in[9];
    const float* W_ih      = (const float*)d_in[10];
    const float* W_hh      = (const float*)d_in[11];
    const float* b_ih      = (const float*)d_in[12];
    const float* b_hh      = (const float*)d_in[13];
    const float* out_W     = (const float*)d_in[14];
    const float* out_b     = (const float*)d_in[15];
    float* out = (float*)d_out;

    cudaFuncSetAttribute(megastep, cudaFuncAttributeMaxDynamicSharedMemorySize, DSM_BYTES);

    build_u_kernel<<<(NN * 256 + 255) / 256, 256>>>(m_seq, tf_seq, tj_seq);
    build_w_kernel<<<(384*512 + 3*3*4*128 + 256*768 + 255) / 256, 256>>>(W_msg, W_ih, W_hh);
    rownorm_kernel<<<NN, 256>>>(A);
    init_kernel<<<(NN * 128 + 255) / 256, 256>>>();
    gemmA2<<<dim3(32, 32), 256>>>();                 // A2 = Anorm^2 (one-time)
    gemmP12<<<dim3(2, 32, 2), 256>>>();              // P1 and P2 in one launch

    megastep<<<NCTA, 256, DSM_BYTES>>>(x_seq, m_seq, tf_seq, tj_seq, b_msg, mix_b,
                                       path_bias, W_ih, b_ih, b_hh, out_W, out_b,
                                       mix_W, out);
}